// round 1
// baseline (speedup 1.0000x reference)
#include <cuda_runtime.h>
#include <cuda_bf16.h>

#define B_IMG 48
#define H_DIM 512
#define W_DIM 512
#define K_K   33
#define N_PIX (H_DIM * W_DIM)
// nonzero hann entries = (K-2)^2 = 961 ; zero-weight pixel count:
#define N_ZERO (N_PIX - 961)

// Scratch (no allocations allowed in kernel_launch)
__device__ float g_sum[B_IMG];   // per-image sum of softplus(pred)
__device__ int   g_y[B_IMG];     // ymin per image
__device__ int   g_x[B_IMG];     // xmin per image
__device__ float g_hsum;         // sum of hann kernel

__device__ __forceinline__ float softplus_f(float x) {
    // stable: max(x,0) + log1p(exp(-|x|))
    return fmaxf(x, 0.0f) + log1pf(__expf(-fabsf(x)));
}

__device__ __forceinline__ float blockReduceSum(float v) {
    __shared__ float sh[32];
    __syncthreads();                       // allow shared reuse across calls
    int lane = threadIdx.x & 31;
    int wid  = threadIdx.x >> 5;
    #pragma unroll
    for (int o = 16; o > 0; o >>= 1) v += __shfl_down_sync(0xffffffffu, v, o);
    if (lane == 0) sh[wid] = v;
    __syncthreads();
    int nw = (blockDim.x + 31) >> 5;
    v = (threadIdx.x < nw) ? sh[lane] : 0.0f;
    if (wid == 0) {
        #pragma unroll
        for (int o = 16; o > 0; o >>= 1) v += __shfl_down_sync(0xffffffffu, v, o);
    }
    return v;   // valid in thread 0
}

// ---------------------------------------------------------------------------
// Kernel 0: init accumulators, locate patch origin per image (sparse sampling),
//           and reduce the hann-kernel sum. Grid = B_IMG + 1 blocks, 256 thr.
// ---------------------------------------------------------------------------
__global__ void k_locate(const float* __restrict__ tgt,
                         const float* __restrict__ hann,
                         float* __restrict__ out) {
    int b = blockIdx.x;
    int t = threadIdx.x;

    if (b == B_IMG) {
        // init block: zero accumulators + output, compute S_hann
        if (t < B_IMG) g_sum[t] = 0.0f;
        if (t == B_IMG) out[0] = 0.0f;
        float s = 0.0f;
        for (int i = t; i < K_K * K_K; i += blockDim.x) s += hann[i];
        s = blockReduceSum(s);
        if (t == 0) g_hsum = s;
        return;
    }

    const float* T = tgt + (size_t)b * N_PIX;

    // 16x16 sample grid at stride 32 always hits the 33x33 block of ones.
    __shared__ int s_min;
    if (t == 0) s_min = 0x7fffffff;
    __syncthreads();

    int sy = (t >> 4) << 5;       // 0,32,...,480
    int sx = (t & 15) << 5;
    if (T[sy * W_DIM + sx] == 1.0f) atomicMin(&s_min, sy * W_DIM + sx);
    __syncthreads();

    int hit = s_min;
    int y0 = hit / W_DIM;
    int x0 = hit - y0 * W_DIM;

    if (t < 32) {
        // refine xmin along row y0: candidates x0-32 .. x0-1 (x0 itself is 1)
        int x = x0 - 32 + t;
        bool one = (x >= 0) && (T[y0 * W_DIM + x] == 1.0f);
        unsigned m = __ballot_sync(0xffffffffu, one);
        if (t == 0) g_x[b] = m ? (x0 - 32 + (__ffs(m) - 1)) : x0;
    } else if (t < 64) {
        int l = t - 32;
        int y = y0 - 32 + l;
        bool one = (y >= 0) && (T[y * W_DIM + x0] == 1.0f);
        unsigned m = __ballot_sync(0xffffffffu, one);
        if (l == 0) g_y[b] = m ? (y0 - 32 + (__ffs(m) - 1)) : y0;
    }
}

// ---------------------------------------------------------------------------
// Kernel 1: per-image sum of softplus(pred).  Grid = (64, B_IMG), 256 thr.
// Memory-bound workhorse: vectorized float4 loads of pred only.
// ---------------------------------------------------------------------------
__global__ void k_sum(const float* __restrict__ pred) {
    int b = blockIdx.y;
    const float4* P = reinterpret_cast<const float4*>(pred + (size_t)b * N_PIX);
    const int n4 = N_PIX / 4;     // 65536

    float s = 0.0f;
    for (int i = blockIdx.x * blockDim.x + threadIdx.x; i < n4;
         i += gridDim.x * blockDim.x) {
        float4 v = P[i];
        s += softplus_f(v.x) + softplus_f(v.y) + softplus_f(v.z) + softplus_f(v.w);
    }
    s = blockReduceSum(s);
    if (threadIdx.x == 0) atomicAdd(&g_sum[b], s);
}

// ---------------------------------------------------------------------------
// Kernel 2: per-image patch sums + final loss combine. Grid = B_IMG, 256 thr.
// ---------------------------------------------------------------------------
__global__ void k_patch(const float* __restrict__ pred,
                        const float* __restrict__ hann,
                        float* __restrict__ out) {
    int b  = blockIdx.x;
    int ys = g_y[b];
    int xs = g_x[b];
    const float* P = pred + (size_t)b * N_PIX;

    float sum_p  = 0.0f;   // sum of pred over full 33x33 patch (target==1 term)
    float sum_zw = 0.0f;   // sum of hann * bce over nonzero-hann positions
    float sum_z  = 0.0f;   // sum of bce over nonzero-hann positions

    for (int i = threadIdx.x; i < K_K * K_K; i += blockDim.x) {
        int r = i / K_K;
        int c = i - r * K_K;
        float p  = P[(ys + r) * W_DIM + (xs + c)];
        float hv = hann[i];
        sum_p += p;
        if (hv != 0.0f) {
            float bce = softplus_f(p) - p;   // target==1 here
            sum_zw += hv * bce;
            sum_z  += bce;
        }
    }

    float r_p  = blockReduceSum(sum_p);
    float r_zw = blockReduceSum(sum_zw);
    float r_z  = blockReduceSum(sum_z);

    if (threadIdx.x == 0) {
        float bce_total = g_sum[b] - r_p;         // sum over all pixels of bce
        float loss = r_zw / (2.0f * g_hsum)
                   + (bce_total - r_z) * (1.0f / (2.0f * (float)N_ZERO));
        atomicAdd(out, loss * (1.0f / (float)B_IMG));
    }
}

extern "C" void kernel_launch(void* const* d_in, const int* in_sizes, int n_in,
                              void* d_out, int out_size) {
    const float* pred = (const float*)d_in[0];
    const float* tgt  = (const float*)d_in[1];
    const float* hann = (const float*)d_in[2];
    float* out = (float*)d_out;

    k_locate<<<B_IMG + 1, 256>>>(tgt, hann, out);
    dim3 grid(64, B_IMG);
    k_sum<<<grid, 256>>>(pred);
    k_patch<<<B_IMG, 256>>>(pred, hann, out);
}

// round 2
// speedup vs baseline: 1.6780x; 1.6780x over previous
#include <cuda_runtime.h>
#include <cuda_bf16.h>

#define B_IMG 48
#define H_DIM 512
#define W_DIM 512
#define K_K   33
#define N_PIX (H_DIM * W_DIM)
#define N_ZERO (N_PIX - 961)          // nonzero hann entries = (K-2)^2 = 961

#define BLKX  32                      // blocks per image
#define THR   256
#define F4_PER_IMG (N_PIX / 4)        // 65536
#define STRIDE (BLKX * THR)           // 8192
#define ITERS  (F4_PER_IMG / STRIDE)  // 8

// Persistent scratch; all values are restored to 0 before kernel exit so
// every graph replay starts from the same state.
__device__ float g_sum[B_IMG];   // per-image sum of softplus(pred)
__device__ int   g_cnt[B_IMG];   // per-image finished-block counter
__device__ float g_loss;         // accumulated loss across images
__device__ int   g_done;         // finished-image counter

__device__ __forceinline__ float softplus_f(float x) {
    // stable: max(x,0) + log(1 + exp(-|x|)); fast MUFU path
    float z = __expf(-fabsf(x));
    return fmaxf(x, 0.0f) + __logf(1.0f + z);
}

__device__ __forceinline__ float blockReduceSum(float v) {
    __shared__ float sh[32];
    __syncthreads();                       // protect shared buffer across calls
    int lane = threadIdx.x & 31;
    int wid  = threadIdx.x >> 5;
    #pragma unroll
    for (int o = 16; o > 0; o >>= 1) v += __shfl_down_sync(0xffffffffu, v, o);
    if (lane == 0) sh[wid] = v;
    __syncthreads();
    int nw = (blockDim.x + 31) >> 5;
    v = (threadIdx.x < nw) ? sh[lane] : 0.0f;
    if (wid == 0) {
        #pragma unroll
        for (int o = 16; o > 0; o >>= 1) v += __shfl_down_sync(0xffffffffu, v, o);
    }
    return v;   // valid in thread 0
}

__global__ void fused_hann_loss(const float* __restrict__ pred,
                                const float* __restrict__ tgt,
                                const float* __restrict__ hann,
                                float* __restrict__ out) {
    const int b = blockIdx.y;
    const int t = threadIdx.x;
    const float* P = pred + (size_t)b * N_PIX;

    // ---- Phase 1: streaming softplus sum over this block's slice ----
    {
        const float4* P4 = reinterpret_cast<const float4*>(P);
        float s = 0.0f;
        int i = blockIdx.x * THR + t;
        #pragma unroll 4
        for (int k = 0; k < ITERS; k++) {
            float4 v = P4[i + k * STRIDE];
            s += softplus_f(v.x) + softplus_f(v.y)
               + softplus_f(v.z) + softplus_f(v.w);
        }
        s = blockReduceSum(s);

        __shared__ int sh_done;
        if (t == 0) {
            atomicAdd(&g_sum[b], s);
            __threadfence();                       // release partial sum
            int old = atomicAdd(&g_cnt[b], 1);
            sh_done = (old == BLKX - 1);
        }
        __syncthreads();
        if (!sh_done) return;                      // uniform branch
    }

    // ---- Phase 2 (last block of image b): locate patch origin ----
    const float* T = tgt + (size_t)b * N_PIX;
    __shared__ int s_min, s_ys, s_xs;
    if (t == 0) s_min = 0x7fffffff;
    __syncthreads();

    // 16x16 sample grid at stride 32 always hits the 33x33 block of ones.
    {
        int sy = (t >> 4) << 5;      // 0,32,...,480
        int sx = (t & 15) << 5;
        if (T[sy * W_DIM + sx] == 1.0f) atomicMin(&s_min, sy * W_DIM + sx);
    }
    __syncthreads();

    int y0 = s_min / W_DIM;
    int x0 = s_min - y0 * W_DIM;

    if (t < 32) {
        // refine xmin along row y0: candidates x0-32 .. x0-1
        int x = x0 - 32 + t;
        bool one = (x >= 0) && (T[y0 * W_DIM + x] == 1.0f);
        unsigned m = __ballot_sync(0xffffffffu, one);
        if (t == 0) s_xs = m ? (x0 - 32 + (__ffs(m) - 1)) : x0;
    } else if (t < 64) {
        int l = t - 32;
        int y = y0 - 32 + l;
        bool one = (y >= 0) && (T[y * W_DIM + x0] == 1.0f);
        unsigned m = __ballot_sync(0xffffffffu, one);
        if (l == 0) s_ys = m ? (y0 - 32 + (__ffs(m) - 1)) : y0;
    }
    __syncthreads();
    const int ys = s_ys;
    const int xs = s_xs;

    // ---- Phase 3: 33x33 patch sums (pred lines hot in L2) ----
    float sum_p  = 0.0f;   // sum pred over patch (target==1 term)
    float sum_zw = 0.0f;   // sum hann * bce over nonzero-hann positions
    float sum_z  = 0.0f;   // sum bce over nonzero-hann positions
    float sum_h  = 0.0f;   // hann kernel sum

    for (int idx = t; idx < K_K * K_K; idx += THR) {
        int r = idx / K_K;
        int c = idx - r * K_K;
        float p  = P[(ys + r) * W_DIM + (xs + c)];
        float hv = hann[idx];
        sum_p += p;
        sum_h += hv;
        if (hv != 0.0f) {
            float bce = softplus_f(p) - p;   // target==1 here
            sum_zw += hv * bce;
            sum_z  += bce;
        }
    }

    float r_p  = blockReduceSum(sum_p);
    float r_zw = blockReduceSum(sum_zw);
    float r_z  = blockReduceSum(sum_z);
    float r_h  = blockReduceSum(sum_h);

    // ---- Phase 4: combine, global accumulate, final write + state reset ----
    if (t == 0) {
        float total_sp = atomicExch(&g_sum[b], 0.0f);   // read-and-reset
        atomicExch(&g_cnt[b], 0);                       // reset counter

        float bce_total = total_sp - r_p;               // sum of bce, all pixels
        float loss = r_zw / (2.0f * r_h)
                   + (bce_total - r_z) * (1.0f / (2.0f * (float)N_ZERO));

        atomicAdd(&g_loss, loss);
        __threadfence();                                // release loss
        int od = atomicAdd(&g_done, 1);
        if (od == B_IMG - 1) {
            float tot = atomicExch(&g_loss, 0.0f);      // read-and-reset
            atomicExch(&g_done, 0);
            out[0] = tot * (1.0f / (float)B_IMG);
        }
    }
}

extern "C" void kernel_launch(void* const* d_in, const int* in_sizes, int n_in,
                              void* d_out, int out_size) {
    const float* pred = (const float*)d_in[0];
    const float* tgt  = (const float*)d_in[1];
    const float* hann = (const float*)d_in[2];
    float* out = (float*)d_out;

    dim3 grid(BLKX, B_IMG);
    fused_hann_loss<<<grid, THR>>>(pred, tgt, hann, out);
}

// round 3
// speedup vs baseline: 1.7106x; 1.0194x over previous
#include <cuda_runtime.h>
#include <cuda_bf16.h>

#define B_IMG 48
#define H_DIM 512
#define W_DIM 512
#define K_K   33
#define N_PIX (H_DIM * W_DIM)
#define N_ZERO (N_PIX - 961)            // nonzero hann entries = (K-2)^2

#define THR      256
#define BLKX     24                     // blocks per image (block 0 = patch block)
#define NSTREAM  (BLKX - 1)             // 23 streaming blocks per image
#define F4_PER_IMG (N_PIX / 4)          // 65536
#define CHUNK ((F4_PER_IMG + NSTREAM - 1) / NSTREAM)   // 2850

// Persistent scratch; reset to 0 before kernel exit => replay-deterministic.
__device__ float g_sum[B_IMG];     // per-image sum of softplus(pred)
__device__ float g_pp [B_IMG];     // patch: sum pred over 33x33
__device__ float g_pzw[B_IMG];     // patch: sum hann*bce (nonzero hann)
__device__ float g_pz [B_IMG];     // patch: sum bce (nonzero hann)
__device__ float g_ph [B_IMG];     // hann sum
__device__ int   g_cnt[B_IMG];     // per-image arrival counter
__device__ float g_loss;           // accumulated loss
__device__ int   g_done;           // finished-image counter

__device__ __forceinline__ float softplus_f(float x) {
    float z = __expf(-fabsf(x));
    return fmaxf(x, 0.0f) + __logf(1.0f + z);
}

__device__ __forceinline__ float blockReduceSum(float v) {
    __shared__ float sh[32];
    __syncthreads();
    int lane = threadIdx.x & 31;
    int wid  = threadIdx.x >> 5;
    #pragma unroll
    for (int o = 16; o > 0; o >>= 1) v += __shfl_down_sync(0xffffffffu, v, o);
    if (lane == 0) sh[wid] = v;
    __syncthreads();
    int nw = (blockDim.x + 31) >> 5;
    v = (threadIdx.x < nw) ? sh[lane] : 0.0f;
    if (wid == 0) {
        #pragma unroll
        for (int o = 16; o > 0; o >>= 1) v += __shfl_down_sync(0xffffffffu, v, o);
    }
    return v;   // valid in thread 0
}

__global__ void __launch_bounds__(THR, 8)
fused_hann_loss(const float* __restrict__ pred,
                const float* __restrict__ tgt,
                const float* __restrict__ hann,
                float* __restrict__ out) {
    const int b  = blockIdx.y;
    const int bx = blockIdx.x;
    const int t  = threadIdx.x;
    const float* P = pred + (size_t)b * N_PIX;

    if (bx != 0) {
        // ---------------- streaming blocks: softplus sum over chunk ----------
        const float4* P4 = reinterpret_cast<const float4*>(P);
        const int beg = (bx - 1) * CHUNK;
        const int end = min(beg + CHUNK, F4_PER_IMG);

        float s = 0.0f;
        int j = beg + t;
        const int lim = end - 3 * THR;
        for (; j < lim; j += 4 * THR) {           // front-batched 4x float4
            float4 a = P4[j];
            float4 c = P4[j +     THR];
            float4 d = P4[j + 2 * THR];
            float4 e = P4[j + 3 * THR];
            s += softplus_f(a.x) + softplus_f(a.y) + softplus_f(a.z) + softplus_f(a.w);
            s += softplus_f(c.x) + softplus_f(c.y) + softplus_f(c.z) + softplus_f(c.w);
            s += softplus_f(d.x) + softplus_f(d.y) + softplus_f(d.z) + softplus_f(d.w);
            s += softplus_f(e.x) + softplus_f(e.y) + softplus_f(e.z) + softplus_f(e.w);
        }
        for (; j < end; j += THR) {
            float4 v = P4[j];
            s += softplus_f(v.x) + softplus_f(v.y) + softplus_f(v.z) + softplus_f(v.w);
        }
        s = blockReduceSum(s);
        if (t == 0) {
            atomicAdd(&g_sum[b], s);
            __threadfence();                      // release partial sum
        }
    } else {
        // ---------------- patch block: locate + 33x33 patch sums -------------
        const float* T = tgt + (size_t)b * N_PIX;
        __shared__ int s_min, s_ys, s_xs;
        if (t == 0) s_min = 0x7fffffff;
        __syncthreads();

        // 16x16 sample grid at stride 32 always hits the 33x33 ones block.
        {
            int sy = (t >> 4) << 5;
            int sx = (t & 15) << 5;
            if (T[sy * W_DIM + sx] == 1.0f) atomicMin(&s_min, sy * W_DIM + sx);
        }
        __syncthreads();

        int y0 = s_min / W_DIM;
        int x0 = s_min - y0 * W_DIM;

        if (t < 32) {
            int x = x0 - 32 + t;
            bool one = (x >= 0) && (T[y0 * W_DIM + x] == 1.0f);
            unsigned m = __ballot_sync(0xffffffffu, one);
            if (t == 0) s_xs = m ? (x0 - 32 + (__ffs(m) - 1)) : x0;
        } else if (t < 64) {
            int l = t - 32;
            int y = y0 - 32 + l;
            bool one = (y >= 0) && (T[y * W_DIM + x0] == 1.0f);
            unsigned m = __ballot_sync(0xffffffffu, one);
            if (l == 0) s_ys = m ? (y0 - 32 + (__ffs(m) - 1)) : y0;
        }
        __syncthreads();
        const int ys = s_ys;
        const int xs = s_xs;

        float sum_p = 0.0f, sum_zw = 0.0f, sum_z = 0.0f, sum_h = 0.0f;
        for (int idx = t; idx < K_K * K_K; idx += THR) {
            int r = idx / K_K;
            int c = idx - r * K_K;
            float p  = P[(ys + r) * W_DIM + (xs + c)];
            float hv = hann[idx];
            sum_p += p;
            sum_h += hv;
            if (hv != 0.0f) {
                float bce = softplus_f(p) - p;    // target==1 on patch
                sum_zw += hv * bce;
                sum_z  += bce;
            }
        }
        float r_p  = blockReduceSum(sum_p);
        float r_zw = blockReduceSum(sum_zw);
        float r_z  = blockReduceSum(sum_z);
        float r_h  = blockReduceSum(sum_h);

        if (t == 0) {
            g_pp [b] = r_p;
            g_pzw[b] = r_zw;
            g_pz [b] = r_z;
            g_ph [b] = r_h;
            __threadfence();                      // release patch results
        }
    }

    // ---------------- arrival + per-image combine (tiny) ---------------------
    if (t == 0) {
        int old = atomicAdd(&g_cnt[b], 1);
        if (old == BLKX - 1) {                    // last arrival for image b
            __threadfence();                      // acquire all published data
            atomicExch(&g_cnt[b], 0);
            float total_sp = atomicExch(&g_sum[b], 0.0f);
            float r_p  = atomicExch(&g_pp [b], 0.0f);
            float r_zw = atomicExch(&g_pzw[b], 0.0f);
            float r_z  = atomicExch(&g_pz [b], 0.0f);
            float r_h  = atomicExch(&g_ph [b], 0.0f);

            float bce_total = total_sp - r_p;
            float loss = r_zw / (2.0f * r_h)
                       + (bce_total - r_z) * (1.0f / (2.0f * (float)N_ZERO));

            atomicAdd(&g_loss, loss);
            __threadfence();
            int od = atomicAdd(&g_done, 1);
            if (od == B_IMG - 1) {
                __threadfence();
                float tot = atomicExch(&g_loss, 0.0f);
                atomicExch(&g_done, 0);
                out[0] = tot * (1.0f / (float)B_IMG);
            }
        }
    }
}

extern "C" void kernel_launch(void* const* d_in, const int* in_sizes, int n_in,
                              void* d_out, int out_size) {
    const float* pred = (const float*)d_in[0];
    const float* tgt  = (const float*)d_in[1];
    const float* hann = (const float*)d_in[2];
    float* out = (float*)d_out;

    dim3 grid(BLKX, B_IMG);
    fused_hann_loss<<<grid, THR>>>(pred, tgt, hann, out);
}